// round 1
// baseline (speedup 1.0000x reference)
#include <cuda_runtime.h>
#include <cstdint>

// Problem-size upper bounds (fixed by the dataset)
#define MAXN 100000
#define MAXE 1600000
#define MAXG 2048
#define H 64

// ---------------- scratch (device globals; no runtime alloc allowed) -------
__device__ float g_h[MAXN * H];        // node features
__device__ float g_z[MAXN * H];        // h + agg (MLP input)
__device__ int   g_cnt[MAXN];          // in-degree histogram
__device__ int   g_off[MAXN + 1];      // CSR offsets by dst
__device__ int   g_cur[MAXN];          // running cursors for fill
__device__ int2  g_adj[MAXE];          // (src, eid) per CSR slot
__device__ float g_sums[MAXG * H];     // graph pooling sums
__device__ float g_cntf[MAXG];         // graph node counts

// ---------------- small utility kernels ------------------------------------
__global__ void zero_int_kernel(int* p, int n) {
    for (int i = blockIdx.x * blockDim.x + threadIdx.x; i < n; i += gridDim.x * blockDim.x)
        p[i] = 0;
}
__global__ void zero_float_kernel(float* p, int n) {
    for (int i = blockIdx.x * blockDim.x + threadIdx.x; i < n; i += gridDim.x * blockDim.x)
        p[i] = 0.f;
}
__global__ void copy_int_kernel(const int* __restrict__ a, int* __restrict__ b, int n) {
    for (int i = blockIdx.x * blockDim.x + threadIdx.x; i < n; i += gridDim.x * blockDim.x)
        b[i] = a[i];
}

// ---------------- CSR build -------------------------------------------------
__global__ void hist_kernel(const int* __restrict__ dst, int nedges) {
    for (int i = blockIdx.x * blockDim.x + threadIdx.x; i < nedges; i += gridDim.x * blockDim.x)
        atomicAdd(&g_cnt[dst[i]], 1);
}

// single-block exclusive scan over g_cnt[0..n) -> g_off, g_off[n] = total
__global__ void scan_kernel(int n) {
    __shared__ int wsum[32];
    __shared__ int s_carry;
    int t = threadIdx.x, lane = t & 31, w = t >> 5;
    if (t == 0) s_carry = 0;
    __syncthreads();
    int nchunk = (n + 1023) >> 10;
    for (int c = 0; c < nchunk; c++) {
        int i = (c << 10) + t;
        int v = (i < n) ? g_cnt[i] : 0;
        int x = v;
        #pragma unroll
        for (int d = 1; d < 32; d <<= 1) {
            int y = __shfl_up_sync(0xffffffffu, x, d);
            if (lane >= d) x += y;
        }
        if (lane == 31) wsum[w] = x;
        __syncthreads();
        if (w == 0) {
            int sv = wsum[lane];
            #pragma unroll
            for (int d = 1; d < 32; d <<= 1) {
                int y = __shfl_up_sync(0xffffffffu, sv, d);
                if (lane >= d) sv += y;
            }
            wsum[lane] = sv;
        }
        __syncthreads();
        int pre = (w == 0) ? 0 : wsum[w - 1];
        int carry = s_carry;
        if (i < n) g_off[i] = carry + pre + x - v;
        __syncthreads();
        if (t == 0) s_carry = carry + wsum[31];
        __syncthreads();
    }
    if (threadIdx.x == 0) g_off[n] = s_carry;
}

__global__ void fill_kernel(const int* __restrict__ src, const int* __restrict__ dst, int nedges) {
    for (int i = blockIdx.x * blockDim.x + threadIdx.x; i < nedges; i += gridDim.x * blockDim.x) {
        int d = dst[i];
        int p = atomicAdd(&g_cur[d], 1);
        g_adj[p] = make_int2(src[i], i);
    }
}

// ---------------- input projection: h = relu(x @ W_in + b_in) --------------
// x: [n,32], W: [32,64]
__global__ void inproj_kernel(const float* __restrict__ x,
                              const float* __restrict__ W, const float* __restrict__ b,
                              int n) {
    __shared__ float sW[32 * 64];
    __shared__ float sb[64];
    __shared__ float sx[4][32];
    int tid = threadIdx.x;
    for (int i = tid; i < 32 * 64; i += 256) sW[i] = W[i];
    if (tid < 64) sb[tid] = b[tid];
    __syncthreads();
    int s = tid >> 6, j = tid & 63;
    int ntiles = (n + 3) >> 2;
    for (int tile = blockIdx.x; tile < ntiles; tile += gridDim.x) {
        int base = tile * 4;
        if (tid < 128) {
            int node = base + (tid >> 5);
            sx[tid >> 5][tid & 31] = (node < n) ? x[(size_t)node * 32 + (tid & 31)] : 0.f;
        }
        __syncthreads();
        float acc = sb[j];
        #pragma unroll
        for (int k = 0; k < 32; k++) acc = fmaf(sx[s][k], sW[k * 64 + j], acc);
        int node = base + s;
        if (node < n) g_h[(size_t)node * H + j] = fmaxf(acc, 0.f);
        __syncthreads();
    }
}

// ---------------- edge aggregation (warp per dst node, no atomics) ---------
// z[n] = h[n] + sum_{edges into n} relu(h[src] + edge_attr[eid] @ We + be)
__global__ void agg_kernel(const float* __restrict__ edge_attr,
                           const float* __restrict__ We, const float* __restrict__ be,
                           int n) {
    __shared__ float sWe[4 * 64];
    __shared__ float sbe[64];
    int tid = threadIdx.x;
    if (tid < 256) sWe[tid] = We[tid];
    if (tid < 64) sbe[tid] = be[tid];
    __syncthreads();
    int lane = tid & 31;
    int warp = (blockIdx.x * blockDim.x + tid) >> 5;
    int nwarps = (gridDim.x * blockDim.x) >> 5;
    int c0 = lane * 2;
    float w00 = sWe[0 * 64 + c0], w10 = sWe[1 * 64 + c0], w20 = sWe[2 * 64 + c0], w30 = sWe[3 * 64 + c0];
    float w01 = sWe[0 * 64 + c0 + 1], w11 = sWe[1 * 64 + c0 + 1], w21 = sWe[2 * 64 + c0 + 1], w31 = sWe[3 * 64 + c0 + 1];
    float bb0 = sbe[c0], bb1 = sbe[c0 + 1];
    for (int node = warp; node < n; node += nwarps) {
        int s = g_off[node], e = g_off[node + 1];
        float a0 = 0.f, a1 = 0.f;
        for (int p = s; p < e; ++p) {
            int2 se = g_adj[p];
            float4 ea = __ldg((const float4*)(edge_attr + (size_t)se.y * 4));
            float2 hv = __ldg((const float2*)(g_h + (size_t)se.x * H + c0));
            float e0 = bb0 + ea.x * w00 + ea.y * w10 + ea.z * w20 + ea.w * w30;
            float e1 = bb1 + ea.x * w01 + ea.y * w11 + ea.z * w21 + ea.w * w31;
            a0 += fmaxf(hv.x + e0, 0.f);
            a1 += fmaxf(hv.y + e1, 0.f);
        }
        float2 hd = *(const float2*)(g_h + (size_t)node * H + c0);
        float2 outv;
        outv.x = hd.x + a0;
        outv.y = hd.y + a1;
        *(float2*)(g_z + (size_t)node * H + c0) = outv;
    }
}

// ---------------- node MLP: h = relu( relu(z@W1+b1) @ W2 + b2 ) ------------
__global__ void mlp_kernel(const float* __restrict__ W1, const float* __restrict__ b1,
                           const float* __restrict__ W2, const float* __restrict__ b2,
                           int n) {
    __shared__ float sW1[64 * 64], sW2[64 * 64];
    __shared__ float sb1[64], sb2[64];
    __shared__ float sz[4][64], st[4][64];
    int tid = threadIdx.x;
    for (int i = tid; i < 64 * 64; i += 256) { sW1[i] = W1[i]; sW2[i] = W2[i]; }
    if (tid < 64) { sb1[tid] = b1[tid]; sb2[tid] = b2[tid]; }
    __syncthreads();
    int s = tid >> 6, j = tid & 63;
    int ntiles = (n + 3) >> 2;
    for (int tile = blockIdx.x; tile < ntiles; tile += gridDim.x) {
        int base = tile * 4;
        {
            int node = base + (tid >> 6);
            sz[tid >> 6][tid & 63] = (node < n) ? g_z[(size_t)node * H + (tid & 63)] : 0.f;
        }
        __syncthreads();
        float acc0 = sb1[j], acc1 = 0.f;
        #pragma unroll
        for (int k = 0; k < 64; k += 2) {
            acc0 = fmaf(sz[s][k], sW1[k * 64 + j], acc0);
            acc1 = fmaf(sz[s][k + 1], sW1[(k + 1) * 64 + j], acc1);
        }
        st[s][j] = fmaxf(acc0 + acc1, 0.f);
        __syncthreads();
        float bcc0 = sb2[j], bcc1 = 0.f;
        #pragma unroll
        for (int k = 0; k < 64; k += 2) {
            bcc0 = fmaf(st[s][k], sW2[k * 64 + j], bcc0);
            bcc1 = fmaf(st[s][k + 1], sW2[(k + 1) * 64 + j], bcc1);
        }
        int node = base + s;
        if (node < n) g_h[(size_t)node * H + j] = fmaxf(bcc0 + bcc1, 0.f);
        __syncthreads();
    }
}

// ---------------- pooling: segment sums + counts ----------------------------
__global__ void pool_kernel(const int* __restrict__ batch, int n) {
    int total = n * H;
    for (int i = blockIdx.x * blockDim.x + threadIdx.x; i < total; i += gridDim.x * blockDim.x) {
        int node = i >> 6, c = i & 63;
        int g = batch[node];
        atomicAdd(&g_sums[g * H + c], g_h[i]);
        if (c == 0) atomicAdd(&g_cntf[g], 1.f);
    }
}

// ---------------- final: mean-pool, layernorm, linear ------------------------
__global__ void final_kernel(float* __restrict__ out,
                             const float* __restrict__ Wout, const float* __restrict__ bout,
                             int G) {
    int warp = (blockIdx.x * blockDim.x + threadIdx.x) >> 5;
    int lane = threadIdx.x & 31;
    if (warp >= G) return;
    float cnt = fmaxf(g_cntf[warp], 1.f);
    float inv = 1.f / cnt;
    int c0 = 2 * lane;
    float v0 = g_sums[warp * H + c0] * inv;
    float v1 = g_sums[warp * H + c0 + 1] * inv;
    float sum = v0 + v1;
    #pragma unroll
    for (int d = 16; d > 0; d >>= 1) sum += __shfl_xor_sync(0xffffffffu, sum, d);
    float mu = sum * (1.f / 64.f);
    float d0 = v0 - mu, d1 = v1 - mu;
    float var = d0 * d0 + d1 * d1;
    #pragma unroll
    for (int d = 16; d > 0; d >>= 1) var += __shfl_xor_sync(0xffffffffu, var, d);
    var *= (1.f / 64.f);
    float rstd = rsqrtf(var + 1e-5f);
    float y = d0 * rstd * Wout[c0] + d1 * rstd * Wout[c0 + 1];
    #pragma unroll
    for (int d = 16; d > 0; d >>= 1) y += __shfl_xor_sync(0xffffffffu, y, d);
    if (lane == 0) out[warp] = y + bout[0];
}

// ---------------- driver -----------------------------------------------------
extern "C" void kernel_launch(void* const* d_in, const int* in_sizes, int n_in,
                              void* d_out, int out_size) {
    const float* x         = (const float*)d_in[0];
    const int*   edge_index= (const int*)  d_in[1];
    const float* edge_attr = (const float*)d_in[2];
    const int*   batch     = (const int*)  d_in[3];
    const float* W_in      = (const float*)d_in[4];
    const float* b_in      = (const float*)d_in[5];
    const float* We        = (const float*)d_in[6];
    const float* be        = (const float*)d_in[7];
    const float* W1        = (const float*)d_in[8];
    const float* b1        = (const float*)d_in[9];
    const float* W2        = (const float*)d_in[10];
    const float* b2        = (const float*)d_in[11];
    const float* W_out     = (const float*)d_in[12];
    const float* b_out     = (const float*)d_in[13];
    float* out = (float*)d_out;

    int N = in_sizes[0] / 32;
    int E = in_sizes[1] / 2;
    int G = out_size;
    const int* src = edge_index;
    const int* dst = edge_index + E;

    int* p_cnt;  cudaGetSymbolAddress((void**)&p_cnt,  g_cnt);
    int* p_off;  cudaGetSymbolAddress((void**)&p_off,  g_off);
    int* p_cur;  cudaGetSymbolAddress((void**)&p_cur,  g_cur);
    float* p_sums; cudaGetSymbolAddress((void**)&p_sums, g_sums);
    float* p_cntf; cudaGetSymbolAddress((void**)&p_cntf, g_cntf);

    // --- CSR build by dst (edges constant across layers) ---
    zero_int_kernel<<<400, 256>>>(p_cnt, N);
    hist_kernel<<<2048, 256>>>(dst, E);
    scan_kernel<<<1, 1024>>>(N);
    copy_int_kernel<<<400, 256>>>(p_off, p_cur, N);
    fill_kernel<<<2048, 256>>>(src, dst, E);

    // --- input projection ---
    inproj_kernel<<<1184, 256>>>(x, W_in, b_in, N);

    // --- 5 GINE layers ---
    for (int l = 0; l < 5; ++l) {
        agg_kernel<<<(N + 7) / 8, 256>>>(edge_attr, We + l * 4 * 64, be + l * 64, N);
        mlp_kernel<<<1184, 256>>>(W1 + l * 64 * 64, b1 + l * 64,
                                  W2 + l * 64 * 64, b2 + l * 64, N);
    }

    // --- global mean pool + layernorm + output ---
    zero_float_kernel<<<256, 256>>>(p_sums, G * H);
    zero_float_kernel<<<16, 256>>>(p_cntf, G);
    pool_kernel<<<4096, 256>>>(batch, N);
    final_kernel<<<(G * 32 + 255) / 256, 256>>>(out, W_out, b_out, G);
}

// round 2
// speedup vs baseline: 1.3613x; 1.3613x over previous
#include <cuda_runtime.h>
#include <cstdint>

// Problem-size upper bounds (fixed by the dataset)
#define MAXN 100000
#define MAXE 1600000
#define MAXG 2048
#define H 64

// ---------------- scratch (device globals; no runtime alloc allowed) -------
__device__ float  g_h[MAXN * H];        // node features
__device__ float  g_z[MAXN * H];        // h + agg (MLP input)
__device__ int    g_cnt[MAXN];          // in-degree histogram
__device__ int    g_off[MAXN + 1];      // CSR offsets by dst
__device__ int    g_cur[MAXN];          // running cursors for fill
__device__ int    g_src[MAXE];          // CSR-ordered source node ids
__device__ float4 g_ea[MAXE];           // CSR-ordered edge attributes
__device__ float  g_sums[MAXG * H];     // graph pooling sums
__device__ float  g_cntf[MAXG];         // graph node counts

// ---------------- small utility kernels ------------------------------------
__global__ void zero_int_kernel(int* p, int n) {
    for (int i = blockIdx.x * blockDim.x + threadIdx.x; i < n; i += gridDim.x * blockDim.x)
        p[i] = 0;
}
__global__ void zero_float_kernel(float* p, int n) {
    for (int i = blockIdx.x * blockDim.x + threadIdx.x; i < n; i += gridDim.x * blockDim.x)
        p[i] = 0.f;
}
__global__ void copy_int_kernel(const int* __restrict__ a, int* __restrict__ b, int n) {
    for (int i = blockIdx.x * blockDim.x + threadIdx.x; i < n; i += gridDim.x * blockDim.x)
        b[i] = a[i];
}

// ---------------- CSR build -------------------------------------------------
__global__ void hist_kernel(const int* __restrict__ dst, int nedges) {
    for (int i = blockIdx.x * blockDim.x + threadIdx.x; i < nedges; i += gridDim.x * blockDim.x)
        atomicAdd(&g_cnt[dst[i]], 1);
}

// single-block exclusive scan over g_cnt[0..n) -> g_off, g_off[n] = total
__global__ void scan_kernel(int n) {
    __shared__ int wsum[32];
    __shared__ int s_carry;
    int t = threadIdx.x, lane = t & 31, w = t >> 5;
    if (t == 0) s_carry = 0;
    __syncthreads();
    int nchunk = (n + 1023) >> 10;
    for (int c = 0; c < nchunk; c++) {
        int i = (c << 10) + t;
        int v = (i < n) ? g_cnt[i] : 0;
        int x = v;
        #pragma unroll
        for (int d = 1; d < 32; d <<= 1) {
            int y = __shfl_up_sync(0xffffffffu, x, d);
            if (lane >= d) x += y;
        }
        if (lane == 31) wsum[w] = x;
        __syncthreads();
        if (w == 0) {
            int sv = wsum[lane];
            #pragma unroll
            for (int d = 1; d < 32; d <<= 1) {
                int y = __shfl_up_sync(0xffffffffu, sv, d);
                if (lane >= d) sv += y;
            }
            wsum[lane] = sv;
        }
        __syncthreads();
        int pre = (w == 0) ? 0 : wsum[w - 1];
        int carry = s_carry;
        if (i < n) g_off[i] = carry + pre + x - v;
        __syncthreads();
        if (t == 0) s_carry = carry + wsum[31];
        __syncthreads();
    }
    if (threadIdx.x == 0) g_off[n] = s_carry;
}

// fill CSR: also pre-sort edge_attr and src into CSR order so the 5 agg
// passes read them as contiguous streams.
__global__ void fill_kernel(const int* __restrict__ src, const int* __restrict__ dst,
                            const float* __restrict__ edge_attr, int nedges) {
    for (int i = blockIdx.x * blockDim.x + threadIdx.x; i < nedges; i += gridDim.x * blockDim.x) {
        int d = dst[i];
        int p = atomicAdd(&g_cur[d], 1);
        g_src[p] = src[i];
        g_ea[p] = __ldg((const float4*)(edge_attr + (size_t)i * 4));
    }
}

// ---------------- input projection: h = relu(x @ W_in + b_in) --------------
// x: [n,32], W: [32,64]
__global__ void inproj_kernel(const float* __restrict__ x,
                              const float* __restrict__ W, const float* __restrict__ b,
                              int n) {
    __shared__ float sW[32 * 64];
    __shared__ float sb[64];
    __shared__ float sx[4][32];
    int tid = threadIdx.x;
    for (int i = tid; i < 32 * 64; i += 256) sW[i] = W[i];
    if (tid < 64) sb[tid] = b[tid];
    __syncthreads();
    int s = tid >> 6, j = tid & 63;
    int ntiles = (n + 3) >> 2;
    for (int tile = blockIdx.x; tile < ntiles; tile += gridDim.x) {
        int base = tile * 4;
        if (tid < 128) {
            int node = base + (tid >> 5);
            sx[tid >> 5][tid & 31] = (node < n) ? x[(size_t)node * 32 + (tid & 31)] : 0.f;
        }
        __syncthreads();
        float acc = sb[j];
        #pragma unroll
        for (int k = 0; k < 32; k++) acc = fmaf(sx[s][k], sW[k * 64 + j], acc);
        int node = base + s;
        if (node < n) g_h[(size_t)node * H + j] = fmaxf(acc, 0.f);
        __syncthreads();
    }
}

// ---------------- edge aggregation (warp per dst node, no atomics) ---------
// z[n] = h[n] + sum_{edges into n} relu(h[src] + ea @ We + be)
__global__ void agg_kernel(const float* __restrict__ We, const float* __restrict__ be,
                           int n) {
    __shared__ float sWe[4 * 64];
    __shared__ float sbe[64];
    int tid = threadIdx.x;
    if (tid < 256) sWe[tid] = We[tid];
    if (tid < 64) sbe[tid] = be[tid];
    __syncthreads();
    int lane = tid & 31;
    int warp = (blockIdx.x * blockDim.x + tid) >> 5;
    int nwarps = (gridDim.x * blockDim.x) >> 5;
    int c0 = lane * 2;
    float w00 = sWe[0 * 64 + c0], w10 = sWe[1 * 64 + c0], w20 = sWe[2 * 64 + c0], w30 = sWe[3 * 64 + c0];
    float w01 = sWe[0 * 64 + c0 + 1], w11 = sWe[1 * 64 + c0 + 1], w21 = sWe[2 * 64 + c0 + 1], w31 = sWe[3 * 64 + c0 + 1];
    float bb0 = sbe[c0], bb1 = sbe[c0 + 1];
    for (int node = warp; node < n; node += nwarps) {
        int s = g_off[node], e = g_off[node + 1];
        float a0 = 0.f, a1 = 0.f;
        for (int p = s; p < e; ++p) {
            int srcn = __ldg(&g_src[p]);
            float4 ea = __ldg(&g_ea[p]);
            float2 hv = __ldg((const float2*)(g_h + (size_t)srcn * H + c0));
            float e0 = bb0 + ea.x * w00 + ea.y * w10 + ea.z * w20 + ea.w * w30;
            float e1 = bb1 + ea.x * w01 + ea.y * w11 + ea.z * w21 + ea.w * w31;
            a0 += fmaxf(hv.x + e0, 0.f);
            a1 += fmaxf(hv.y + e1, 0.f);
        }
        float2 hd = *(const float2*)(g_h + (size_t)node * H + c0);
        float2 outv;
        outv.x = hd.x + a0;
        outv.y = hd.y + a1;
        *(float2*)(g_z + (size_t)node * H + c0) = outv;
    }
}

// ---------------- node MLP: h = relu( relu(z@W1+b1) @ W2 + b2 ) ------------
// 256 threads, 32 nodes/tile. Thread: 2 nodes (i0, i0+16) x 4 outputs (float4).
// All weight reads are LDS.128; z reads are float4 broadcasts -> FMA-bound.
#define TILE_NODES 32
__global__ void __launch_bounds__(256) mlp_kernel(
        const float* __restrict__ W1, const float* __restrict__ b1,
        const float* __restrict__ W2, const float* __restrict__ b2,
        int n, int ntiles) {
    __shared__ float sW1[64 * 64];
    __shared__ float sW2[64 * 64];
    __shared__ float sz[TILE_NODES][64];
    int tid = threadIdx.x;
    for (int i = tid; i < 64 * 64; i += 256) { sW1[i] = W1[i]; sW2[i] = W2[i]; }
    int jgrp = tid & 15;   // output group: j = jgrp*4
    int i0 = tid >> 4;     // node slot 0..15 (second node = i0+16)
    float4 b1v = __ldg((const float4*)(b1 + jgrp * 4));
    float4 b2v = __ldg((const float4*)(b2 + jgrp * 4));
    __syncthreads();
    const float4* W14 = (const float4*)sW1;
    const float4* W24 = (const float4*)sW2;

    for (int tile = blockIdx.x; tile < ntiles; tile += gridDim.x) {
        int base = tile * TILE_NODES;
        // stage z tile: 32 nodes x 64 floats = 512 float4
        {
            const float4* zsrc = (const float4*)(g_z + (size_t)base * H);
            float4* zdst = (float4*)sz;
            long limit = ((long)n - base) * 16;
            #pragma unroll
            for (int r = 0; r < 2; r++) {
                int idx = tid + 256 * r;
                zdst[idx] = (idx < limit) ? zsrc[idx] : make_float4(0.f, 0.f, 0.f, 0.f);
            }
        }
        __syncthreads();
        // ---- GEMV1: t = relu(z @ W1 + b1)
        float4 a0 = b1v, a1 = b1v;
        #pragma unroll
        for (int k4 = 0; k4 < 16; k4++) {
            float4 z0 = *(const float4*)&sz[i0][k4 * 4];
            float4 z1 = *(const float4*)&sz[i0 + 16][k4 * 4];
            float4 w;
            w = W14[(k4 * 4 + 0) * 16 + jgrp];
            a0.x = fmaf(z0.x, w.x, a0.x); a0.y = fmaf(z0.x, w.y, a0.y);
            a0.z = fmaf(z0.x, w.z, a0.z); a0.w = fmaf(z0.x, w.w, a0.w);
            a1.x = fmaf(z1.x, w.x, a1.x); a1.y = fmaf(z1.x, w.y, a1.y);
            a1.z = fmaf(z1.x, w.z, a1.z); a1.w = fmaf(z1.x, w.w, a1.w);
            w = W14[(k4 * 4 + 1) * 16 + jgrp];
            a0.x = fmaf(z0.y, w.x, a0.x); a0.y = fmaf(z0.y, w.y, a0.y);
            a0.z = fmaf(z0.y, w.z, a0.z); a0.w = fmaf(z0.y, w.w, a0.w);
            a1.x = fmaf(z1.y, w.x, a1.x); a1.y = fmaf(z1.y, w.y, a1.y);
            a1.z = fmaf(z1.y, w.z, a1.z); a1.w = fmaf(z1.y, w.w, a1.w);
            w = W14[(k4 * 4 + 2) * 16 + jgrp];
            a0.x = fmaf(z0.z, w.x, a0.x); a0.y = fmaf(z0.z, w.y, a0.y);
            a0.z = fmaf(z0.z, w.z, a0.z); a0.w = fmaf(z0.z, w.w, a0.w);
            a1.x = fmaf(z1.z, w.x, a1.x); a1.y = fmaf(z1.z, w.y, a1.y);
            a1.z = fmaf(z1.z, w.z, a1.z); a1.w = fmaf(z1.z, w.w, a1.w);
            w = W14[(k4 * 4 + 3) * 16 + jgrp];
            a0.x = fmaf(z0.w, w.x, a0.x); a0.y = fmaf(z0.w, w.y, a0.y);
            a0.z = fmaf(z0.w, w.z, a0.z); a0.w = fmaf(z0.w, w.w, a0.w);
            a1.x = fmaf(z1.w, w.x, a1.x); a1.y = fmaf(z1.w, w.y, a1.y);
            a1.z = fmaf(z1.w, w.z, a1.z); a1.w = fmaf(z1.w, w.w, a1.w);
        }
        a0.x = fmaxf(a0.x, 0.f); a0.y = fmaxf(a0.y, 0.f); a0.z = fmaxf(a0.z, 0.f); a0.w = fmaxf(a0.w, 0.f);
        a1.x = fmaxf(a1.x, 0.f); a1.y = fmaxf(a1.y, 0.f); a1.z = fmaxf(a1.z, 0.f); a1.w = fmaxf(a1.w, 0.f);
        __syncthreads();
        *(float4*)&sz[i0][jgrp * 4] = a0;
        *(float4*)&sz[i0 + 16][jgrp * 4] = a1;
        __syncthreads();
        // ---- GEMV2: h = relu(t @ W2 + b2)
        float4 c0 = b2v, c1 = b2v;
        #pragma unroll
        for (int k4 = 0; k4 < 16; k4++) {
            float4 z0 = *(const float4*)&sz[i0][k4 * 4];
            float4 z1 = *(const float4*)&sz[i0 + 16][k4 * 4];
            float4 w;
            w = W24[(k4 * 4 + 0) * 16 + jgrp];
            c0.x = fmaf(z0.x, w.x, c0.x); c0.y = fmaf(z0.x, w.y, c0.y);
            c0.z = fmaf(z0.x, w.z, c0.z); c0.w = fmaf(z0.x, w.w, c0.w);
            c1.x = fmaf(z1.x, w.x, c1.x); c1.y = fmaf(z1.x, w.y, c1.y);
            c1.z = fmaf(z1.x, w.z, c1.z); c1.w = fmaf(z1.x, w.w, c1.w);
            w = W24[(k4 * 4 + 1) * 16 + jgrp];
            c0.x = fmaf(z0.y, w.x, c0.x); c0.y = fmaf(z0.y, w.y, c0.y);
            c0.z = fmaf(z0.y, w.z, c0.z); c0.w = fmaf(z0.y, w.w, c0.w);
            c1.x = fmaf(z1.y, w.x, c1.x); c1.y = fmaf(z1.y, w.y, c1.y);
            c1.z = fmaf(z1.y, w.z, c1.z); c1.w = fmaf(z1.y, w.w, c1.w);
            w = W24[(k4 * 4 + 2) * 16 + jgrp];
            c0.x = fmaf(z0.z, w.x, c0.x); c0.y = fmaf(z0.z, w.y, c0.y);
            c0.z = fmaf(z0.z, w.z, c0.z); c0.w = fmaf(z0.z, w.w, c0.w);
            c1.x = fmaf(z1.z, w.x, c1.x); c1.y = fmaf(z1.z, w.y, c1.y);
            c1.z = fmaf(z1.z, w.z, c1.z); c1.w = fmaf(z1.z, w.w, c1.w);
            w = W24[(k4 * 4 + 3) * 16 + jgrp];
            c0.x = fmaf(z0.w, w.x, c0.x); c0.y = fmaf(z0.w, w.y, c0.y);
            c0.z = fmaf(z0.w, w.z, c0.z); c0.w = fmaf(z0.w, w.w, c0.w);
            c1.x = fmaf(z1.w, w.x, c1.x); c1.y = fmaf(z1.w, w.y, c1.y);
            c1.z = fmaf(z1.w, w.z, c1.z); c1.w = fmaf(z1.w, w.w, c1.w);
        }
        c0.x = fmaxf(c0.x, 0.f); c0.y = fmaxf(c0.y, 0.f); c0.z = fmaxf(c0.z, 0.f); c0.w = fmaxf(c0.w, 0.f);
        c1.x = fmaxf(c1.x, 0.f); c1.y = fmaxf(c1.y, 0.f); c1.z = fmaxf(c1.z, 0.f); c1.w = fmaxf(c1.w, 0.f);
        int n0 = base + i0, n1 = base + i0 + 16;
        if (n0 < n) *(float4*)(g_h + (size_t)n0 * H + jgrp * 4) = c0;
        if (n1 < n) *(float4*)(g_h + (size_t)n1 * H + jgrp * 4) = c1;
        __syncthreads();
    }
}

// ---------------- pooling: segment sums + counts ----------------------------
__global__ void pool_kernel(const int* __restrict__ batch, int n) {
    int total = n * H;
    for (int i = blockIdx.x * blockDim.x + threadIdx.x; i < total; i += gridDim.x * blockDim.x) {
        int node = i >> 6, c = i & 63;
        int g = batch[node];
        atomicAdd(&g_sums[g * H + c], g_h[i]);
        if (c == 0) atomicAdd(&g_cntf[g], 1.f);
    }
}

// ---------------- final: mean-pool, layernorm, linear ------------------------
__global__ void final_kernel(float* __restrict__ out,
                             const float* __restrict__ Wout, const float* __restrict__ bout,
                             int G) {
    int warp = (blockIdx.x * blockDim.x + threadIdx.x) >> 5;
    int lane = threadIdx.x & 31;
    if (warp >= G) return;
    float cnt = fmaxf(g_cntf[warp], 1.f);
    float inv = 1.f / cnt;
    int c0 = 2 * lane;
    float v0 = g_sums[warp * H + c0] * inv;
    float v1 = g_sums[warp * H + c0 + 1] * inv;
    float sum = v0 + v1;
    #pragma unroll
    for (int d = 16; d > 0; d >>= 1) sum += __shfl_xor_sync(0xffffffffu, sum, d);
    float mu = sum * (1.f / 64.f);
    float d0 = v0 - mu, d1 = v1 - mu;
    float var = d0 * d0 + d1 * d1;
    #pragma unroll
    for (int d = 16; d > 0; d >>= 1) var += __shfl_xor_sync(0xffffffffu, var, d);
    var *= (1.f / 64.f);
    float rstd = rsqrtf(var + 1e-5f);
    float y = d0 * rstd * Wout[c0] + d1 * rstd * Wout[c0 + 1];
    #pragma unroll
    for (int d = 16; d > 0; d >>= 1) y += __shfl_xor_sync(0xffffffffu, y, d);
    if (lane == 0) out[warp] = y + bout[0];
}

// ---------------- driver -----------------------------------------------------
extern "C" void kernel_launch(void* const* d_in, const int* in_sizes, int n_in,
                              void* d_out, int out_size) {
    const float* x         = (const float*)d_in[0];
    const int*   edge_index= (const int*)  d_in[1];
    const float* edge_attr = (const float*)d_in[2];
    const int*   batch     = (const int*)  d_in[3];
    const float* W_in      = (const float*)d_in[4];
    const float* b_in      = (const float*)d_in[5];
    const float* We        = (const float*)d_in[6];
    const float* be        = (const float*)d_in[7];
    const float* W1        = (const float*)d_in[8];
    const float* b1        = (const float*)d_in[9];
    const float* W2        = (const float*)d_in[10];
    const float* b2        = (const float*)d_in[11];
    const float* W_out     = (const float*)d_in[12];
    const float* b_out     = (const float*)d_in[13];
    float* out = (float*)d_out;

    int N = in_sizes[0] / 32;
    int E = in_sizes[1] / 2;
    int G = out_size;
    const int* src = edge_index;
    const int* dst = edge_index + E;

    int* p_cnt;  cudaGetSymbolAddress((void**)&p_cnt,  g_cnt);
    int* p_off;  cudaGetSymbolAddress((void**)&p_off,  g_off);
    int* p_cur;  cudaGetSymbolAddress((void**)&p_cur,  g_cur);
    float* p_sums; cudaGetSymbolAddress((void**)&p_sums, g_sums);
    float* p_cntf; cudaGetSymbolAddress((void**)&p_cntf, g_cntf);

    // --- CSR build by dst (edges constant across layers) ---
    zero_int_kernel<<<400, 256>>>(p_cnt, N);
    hist_kernel<<<2048, 256>>>(dst, E);
    scan_kernel<<<1, 1024>>>(N);
    copy_int_kernel<<<400, 256>>>(p_off, p_cur, N);
    fill_kernel<<<2048, 256>>>(src, dst, edge_attr, E);

    // --- input projection ---
    inproj_kernel<<<1184, 256>>>(x, W_in, b_in, N);

    // --- 5 GINE layers ---
    int ntiles = (N + TILE_NODES - 1) / TILE_NODES;
    for (int l = 0; l < 5; ++l) {
        agg_kernel<<<(N + 7) / 8, 256>>>(We + l * 4 * 64, be + l * 64, N);
        mlp_kernel<<<740, 256>>>(W1 + l * 64 * 64, b1 + l * 64,
                                 W2 + l * 64 * 64, b2 + l * 64, N, ntiles);
    }

    // --- global mean pool + layernorm + output ---
    zero_float_kernel<<<256, 256>>>(p_sums, G * H);
    zero_float_kernel<<<16, 256>>>(p_cntf, G);
    pool_kernel<<<4096, 256>>>(batch, N);
    final_kernel<<<(G * 32 + 255) / 256, 256>>>(out, W_out, b_out, G);
}

// round 3
// speedup vs baseline: 1.4703x; 1.0801x over previous
#include <cuda_runtime.h>
#include <cstdint>

#define MAXN 100000
#define MAXE 1600000
#define MAXG 2048
#define H 64

// ---------------- scratch (device globals; no runtime alloc allowed) -------
__device__ float  g_h[MAXN * H];        // node features
__device__ float  g_z[MAXN * H];        // h + agg (MLP input)
__device__ int    g_cnt[MAXN];          // in-degree histogram
__device__ int    g_off[MAXN + 1];      // CSR offsets by dst
__device__ int    g_cur[MAXN];          // running cursors for fill
__device__ int    g_src[MAXE];          // CSR-ordered source node ids
__device__ float4 g_ea[MAXE];           // CSR-ordered edge attributes
__device__ float  g_sums[MAXG * H];     // graph pooling sums
__device__ float  g_cntf[MAXG];         // graph node counts
__device__ int    g_tilectr[8];         // per-launch MLP tile-steal counters

// ---------------- init: zero everything that needs zeroing ------------------
__global__ void init_kernel(int n_cnt, int n_sums) {
    int i = blockIdx.x * blockDim.x + threadIdx.x;
    int stride = gridDim.x * blockDim.x;
    for (int j = i; j < n_cnt; j += stride) g_cnt[j] = 0;
    for (int j = i; j < n_sums; j += stride) g_sums[j] = 0.f;
    if (i < 8) g_tilectr[i] = 0;
}

// ---------------- CSR build -------------------------------------------------
__global__ void hist_kernel(const int* __restrict__ dst, int nedges) {
    for (int i = blockIdx.x * blockDim.x + threadIdx.x; i < nedges; i += gridDim.x * blockDim.x)
        atomicAdd(&g_cnt[dst[i]], 1);
}

// single-block exclusive scan over g_cnt[0..n) -> g_off AND g_cur
__global__ void scan_kernel(int n) {
    __shared__ int wsum[32];
    __shared__ int s_carry;
    int t = threadIdx.x, lane = t & 31, w = t >> 5;
    if (t == 0) s_carry = 0;
    __syncthreads();
    int nchunk = (n + 1023) >> 10;
    for (int c = 0; c < nchunk; c++) {
        int i = (c << 10) + t;
        int v = (i < n) ? g_cnt[i] : 0;
        int x = v;
        #pragma unroll
        for (int d = 1; d < 32; d <<= 1) {
            int y = __shfl_up_sync(0xffffffffu, x, d);
            if (lane >= d) x += y;
        }
        if (lane == 31) wsum[w] = x;
        __syncthreads();
        if (w == 0) {
            int sv = wsum[lane];
            #pragma unroll
            for (int d = 1; d < 32; d <<= 1) {
                int y = __shfl_up_sync(0xffffffffu, sv, d);
                if (lane >= d) sv += y;
            }
            wsum[lane] = sv;
        }
        __syncthreads();
        int pre = (w == 0) ? 0 : wsum[w - 1];
        int carry = s_carry;
        if (i < n) {
            int off = carry + pre + x - v;
            g_off[i] = off;
            g_cur[i] = off;
        }
        __syncthreads();
        if (t == 0) s_carry = carry + wsum[31];
        __syncthreads();
    }
    if (threadIdx.x == 0) g_off[n] = s_carry;
}

// fill CSR: pre-sort edge_attr and src into CSR order
__global__ void fill_kernel(const int* __restrict__ src, const int* __restrict__ dst,
                            const float* __restrict__ edge_attr, int nedges) {
    for (int i = blockIdx.x * blockDim.x + threadIdx.x; i < nedges; i += gridDim.x * blockDim.x) {
        int d = dst[i];
        int p = atomicAdd(&g_cur[d], 1);
        g_src[p] = src[i];
        g_ea[p] = __ldg((const float4*)(edge_attr + (size_t)i * 4));
    }
}

// ---------------- input projection: h = relu(x @ W_in + b_in) --------------
__global__ void inproj_kernel(const float* __restrict__ x,
                              const float* __restrict__ W, const float* __restrict__ b,
                              int n) {
    __shared__ float sW[32 * 64];
    __shared__ float sb[64];
    __shared__ float sx[4][32];
    int tid = threadIdx.x;
    for (int i = tid; i < 32 * 64; i += 256) sW[i] = W[i];
    if (tid < 64) sb[tid] = b[tid];
    __syncthreads();
    int s = tid >> 6, j = tid & 63;
    int ntiles = (n + 3) >> 2;
    for (int tile = blockIdx.x; tile < ntiles; tile += gridDim.x) {
        int base = tile * 4;
        if (tid < 128) {
            int node = base + (tid >> 5);
            sx[tid >> 5][tid & 31] = (node < n) ? x[(size_t)node * 32 + (tid & 31)] : 0.f;
        }
        __syncthreads();
        float acc = sb[j];
        #pragma unroll
        for (int k = 0; k < 32; k++) acc = fmaf(sx[s][k], sW[k * 64 + j], acc);
        int node = base + s;
        if (node < n) g_h[(size_t)node * H + j] = fmaxf(acc, 0.f);
        __syncthreads();
    }
}

// ---------------- edge aggregation (warp per dst node, no atomics) ---------
// z[n] = h[n] + sum_{edges into n} relu(h[src] + ea @ We + be)
// Edge loop unrolled x2 with independent accumulators for MLP of L2 latency.
__global__ void agg_kernel(const float* __restrict__ We, const float* __restrict__ be,
                           int n) {
    __shared__ float sWe[4 * 64];
    __shared__ float sbe[64];
    int tid = threadIdx.x;
    if (tid < 256) sWe[tid] = We[tid];
    if (tid < 64) sbe[tid] = be[tid];
    __syncthreads();
    int lane = tid & 31;
    int warp = (blockIdx.x * blockDim.x + tid) >> 5;
    int nwarps = (gridDim.x * blockDim.x) >> 5;
    int c0 = lane * 2;
    float w00 = sWe[0 * 64 + c0], w10 = sWe[1 * 64 + c0], w20 = sWe[2 * 64 + c0], w30 = sWe[3 * 64 + c0];
    float w01 = sWe[0 * 64 + c0 + 1], w11 = sWe[1 * 64 + c0 + 1], w21 = sWe[2 * 64 + c0 + 1], w31 = sWe[3 * 64 + c0 + 1];
    float bb0 = sbe[c0], bb1 = sbe[c0 + 1];
    for (int node = warp; node < n; node += nwarps) {
        int s = g_off[node], e = g_off[node + 1];
        float a0 = 0.f, a1 = 0.f, d0 = 0.f, d1 = 0.f;
        int p = s;
        for (; p + 2 <= e; p += 2) {
            int s0 = __ldg(&g_src[p]);
            int s1 = __ldg(&g_src[p + 1]);
            float4 q0 = __ldg(&g_ea[p]);
            float4 q1 = __ldg(&g_ea[p + 1]);
            float2 h0 = __ldg((const float2*)(g_h + (size_t)s0 * H + c0));
            float2 h1 = __ldg((const float2*)(g_h + (size_t)s1 * H + c0));
            float e00 = fmaf(q0.x, w00, fmaf(q0.y, w10, fmaf(q0.z, w20, fmaf(q0.w, w30, bb0))));
            float e01 = fmaf(q0.x, w01, fmaf(q0.y, w11, fmaf(q0.z, w21, fmaf(q0.w, w31, bb1))));
            float e10 = fmaf(q1.x, w00, fmaf(q1.y, w10, fmaf(q1.z, w20, fmaf(q1.w, w30, bb0))));
            float e11 = fmaf(q1.x, w01, fmaf(q1.y, w11, fmaf(q1.z, w21, fmaf(q1.w, w31, bb1))));
            a0 += fmaxf(h0.x + e00, 0.f);
            a1 += fmaxf(h0.y + e01, 0.f);
            d0 += fmaxf(h1.x + e10, 0.f);
            d1 += fmaxf(h1.y + e11, 0.f);
        }
        if (p < e) {
            int s0 = __ldg(&g_src[p]);
            float4 q0 = __ldg(&g_ea[p]);
            float2 h0 = __ldg((const float2*)(g_h + (size_t)s0 * H + c0));
            float e00 = fmaf(q0.x, w00, fmaf(q0.y, w10, fmaf(q0.z, w20, fmaf(q0.w, w30, bb0))));
            float e01 = fmaf(q0.x, w01, fmaf(q0.y, w11, fmaf(q0.z, w21, fmaf(q0.w, w31, bb1))));
            a0 += fmaxf(h0.x + e00, 0.f);
            a1 += fmaxf(h0.y + e01, 0.f);
        }
        float2 hd = *(const float2*)(g_h + (size_t)node * H + c0);
        float2 outv;
        outv.x = hd.x + a0 + d0;
        outv.y = hd.y + a1 + d1;
        *(float2*)(g_z + (size_t)node * H + c0) = outv;
    }
}

// ---------------- node MLP: h = relu( relu(z@W1+b1) @ W2 + b2 ) ------------
// Dynamic tile stealing. Optionally fuses the global-mean-pool accumulation
// (last layer): atomicAdd into g_sums instead of writing g_h.
#define TILE_NODES 32
__global__ void __launch_bounds__(256) mlp_kernel(
        const float* __restrict__ W1, const float* __restrict__ b1,
        const float* __restrict__ W2, const float* __restrict__ b2,
        const int* __restrict__ batch, int do_pool,
        int n, int ntiles, int slot) {
    __shared__ float sW1[64 * 64];
    __shared__ float sW2[64 * 64];
    __shared__ float sz[TILE_NODES][64];
    __shared__ int s_tile;
    int tid = threadIdx.x;
    for (int i = tid; i < 64 * 64; i += 256) { sW1[i] = W1[i]; sW2[i] = W2[i]; }
    int jgrp = tid & 15;   // output group: j = jgrp*4
    int i0 = tid >> 4;     // node slot 0..15 (second node = i0+16)
    float4 b1v = __ldg((const float4*)(b1 + jgrp * 4));
    float4 b2v = __ldg((const float4*)(b2 + jgrp * 4));
    __syncthreads();
    const float4* W14 = (const float4*)sW1;
    const float4* W24 = (const float4*)sW2;

    for (;;) {
        if (tid == 0) s_tile = atomicAdd(&g_tilectr[slot], 1);
        __syncthreads();
        int tile = s_tile;
        if (tile >= ntiles) break;
        int base = tile * TILE_NODES;
        // stage z tile: 32 nodes x 64 floats = 512 float4
        {
            const float4* zsrc = (const float4*)(g_z + (size_t)base * H);
            float4* zdst = (float4*)sz;
            long limit = ((long)n - base) * 16;
            #pragma unroll
            for (int r = 0; r < 2; r++) {
                int idx = tid + 256 * r;
                zdst[idx] = (idx < limit) ? zsrc[idx] : make_float4(0.f, 0.f, 0.f, 0.f);
            }
        }
        __syncthreads();
        // ---- GEMV1: t = relu(z @ W1 + b1)
        float4 a0 = b1v, a1 = b1v;
        #pragma unroll
        for (int k4 = 0; k4 < 16; k4++) {
            float4 z0 = *(const float4*)&sz[i0][k4 * 4];
            float4 z1 = *(const float4*)&sz[i0 + 16][k4 * 4];
            float4 w;
            w = W14[(k4 * 4 + 0) * 16 + jgrp];
            a0.x = fmaf(z0.x, w.x, a0.x); a0.y = fmaf(z0.x, w.y, a0.y);
            a0.z = fmaf(z0.x, w.z, a0.z); a0.w = fmaf(z0.x, w.w, a0.w);
            a1.x = fmaf(z1.x, w.x, a1.x); a1.y = fmaf(z1.x, w.y, a1.y);
            a1.z = fmaf(z1.x, w.z, a1.z); a1.w = fmaf(z1.x, w.w, a1.w);
            w = W14[(k4 * 4 + 1) * 16 + jgrp];
            a0.x = fmaf(z0.y, w.x, a0.x); a0.y = fmaf(z0.y, w.y, a0.y);
            a0.z = fmaf(z0.y, w.z, a0.z); a0.w = fmaf(z0.y, w.w, a0.w);
            a1.x = fmaf(z1.y, w.x, a1.x); a1.y = fmaf(z1.y, w.y, a1.y);
            a1.z = fmaf(z1.y, w.z, a1.z); a1.w = fmaf(z1.y, w.w, a1.w);
            w = W14[(k4 * 4 + 2) * 16 + jgrp];
            a0.x = fmaf(z0.z, w.x, a0.x); a0.y = fmaf(z0.z, w.y, a0.y);
            a0.z = fmaf(z0.z, w.z, a0.z); a0.w = fmaf(z0.z, w.w, a0.w);
            a1.x = fmaf(z1.z, w.x, a1.x); a1.y = fmaf(z1.z, w.y, a1.y);
            a1.z = fmaf(z1.z, w.z, a1.z); a1.w = fmaf(z1.z, w.w, a1.w);
            w = W14[(k4 * 4 + 3) * 16 + jgrp];
            a0.x = fmaf(z0.w, w.x, a0.x); a0.y = fmaf(z0.w, w.y, a0.y);
            a0.z = fmaf(z0.w, w.z, a0.z); a0.w = fmaf(z0.w, w.w, a0.w);
            a1.x = fmaf(z1.w, w.x, a1.x); a1.y = fmaf(z1.w, w.y, a1.y);
            a1.z = fmaf(z1.w, w.z, a1.z); a1.w = fmaf(z1.w, w.w, a1.w);
        }
        a0.x = fmaxf(a0.x, 0.f); a0.y = fmaxf(a0.y, 0.f); a0.z = fmaxf(a0.z, 0.f); a0.w = fmaxf(a0.w, 0.f);
        a1.x = fmaxf(a1.x, 0.f); a1.y = fmaxf(a1.y, 0.f); a1.z = fmaxf(a1.z, 0.f); a1.w = fmaxf(a1.w, 0.f);
        __syncthreads();
        *(float4*)&sz[i0][jgrp * 4] = a0;
        *(float4*)&sz[i0 + 16][jgrp * 4] = a1;
        __syncthreads();
        // ---- GEMV2: h = relu(t @ W2 + b2)
        float4 c0 = b2v, c1 = b2v;
        #pragma unroll
        for (int k4 = 0; k4 < 16; k4++) {
            float4 z0 = *(const float4*)&sz[i0][k4 * 4];
            float4 z1 = *(const float4*)&sz[i0 + 16][k4 * 4];
            float4 w;
            w = W24[(k4 * 4 + 0) * 16 + jgrp];
            c0.x = fmaf(z0.x, w.x, c0.x); c0.y = fmaf(z0.x, w.y, c0.y);
            c0.z = fmaf(z0.x, w.z, c0.z); c0.w = fmaf(z0.x, w.w, c0.w);
            c1.x = fmaf(z1.x, w.x, c1.x); c1.y = fmaf(z1.x, w.y, c1.y);
            c1.z = fmaf(z1.x, w.z, c1.z); c1.w = fmaf(z1.x, w.w, c1.w);
            w = W24[(k4 * 4 + 1) * 16 + jgrp];
            c0.x = fmaf(z0.y, w.x, c0.x); c0.y = fmaf(z0.y, w.y, c0.y);
            c0.z = fmaf(z0.y, w.z, c0.z); c0.w = fmaf(z0.y, w.w, c0.w);
            c1.x = fmaf(z1.y, w.x, c1.x); c1.y = fmaf(z1.y, w.y, c1.y);
            c1.z = fmaf(z1.y, w.z, c1.z); c1.w = fmaf(z1.y, w.w, c1.w);
            w = W24[(k4 * 4 + 2) * 16 + jgrp];
            c0.x = fmaf(z0.z, w.x, c0.x); c0.y = fmaf(z0.z, w.y, c0.y);
            c0.z = fmaf(z0.z, w.z, c0.z); c0.w = fmaf(z0.z, w.w, c0.w);
            c1.x = fmaf(z1.z, w.x, c1.x); c1.y = fmaf(z1.z, w.y, c1.y);
            c1.z = fmaf(z1.z, w.z, c1.z); c1.w = fmaf(z1.z, w.w, c1.w);
            w = W24[(k4 * 4 + 3) * 16 + jgrp];
            c0.x = fmaf(z0.w, w.x, c0.x); c0.y = fmaf(z0.w, w.y, c0.y);
            c0.z = fmaf(z0.w, w.z, c0.z); c0.w = fmaf(z0.w, w.w, c0.w);
            c1.x = fmaf(z1.w, w.x, c1.x); c1.y = fmaf(z1.w, w.y, c1.y);
            c1.z = fmaf(z1.w, w.z, c1.z); c1.w = fmaf(z1.w, w.w, c1.w);
        }
        c0.x = fmaxf(c0.x, 0.f); c0.y = fmaxf(c0.y, 0.f); c0.z = fmaxf(c0.z, 0.f); c0.w = fmaxf(c0.w, 0.f);
        c1.x = fmaxf(c1.x, 0.f); c1.y = fmaxf(c1.y, 0.f); c1.z = fmaxf(c1.z, 0.f); c1.w = fmaxf(c1.w, 0.f);
        int n0 = base + i0, n1 = base + i0 + 16;
        if (do_pool) {
            if (n0 < n) {
                int g = __ldg(&batch[n0]);
                float* dstp = g_sums + (size_t)g * H + jgrp * 4;
                atomicAdd(dstp + 0, c0.x); atomicAdd(dstp + 1, c0.y);
                atomicAdd(dstp + 2, c0.z); atomicAdd(dstp + 3, c0.w);
            }
            if (n1 < n) {
                int g = __ldg(&batch[n1]);
                float* dstp = g_sums + (size_t)g * H + jgrp * 4;
                atomicAdd(dstp + 0, c1.x); atomicAdd(dstp + 1, c1.y);
                atomicAdd(dstp + 2, c1.z); atomicAdd(dstp + 3, c1.w);
            }
        } else {
            if (n0 < n) *(float4*)(g_h + (size_t)n0 * H + jgrp * 4) = c0;
            if (n1 < n) *(float4*)(g_h + (size_t)n1 * H + jgrp * 4) = c1;
        }
        __syncthreads();
    }
}

// ---------------- graph node counts via binary search (batch is sorted) -----
__global__ void count_kernel(const int* __restrict__ batch, int n, int G) {
    int g = blockIdx.x * blockDim.x + threadIdx.x;
    if (g >= G) return;
    int lo = 0, hi = n;
    while (lo < hi) { int m = (lo + hi) >> 1; if (batch[m] < g) lo = m + 1; else hi = m; }
    int start = lo;
    lo = 0; hi = n;
    while (lo < hi) { int m = (lo + hi) >> 1; if (batch[m] <= g) lo = m + 1; else hi = m; }
    g_cntf[g] = (float)(lo - start);
}

// ---------------- final: mean-pool, layernorm, linear ------------------------
__global__ void final_kernel(float* __restrict__ out,
                             const float* __restrict__ Wout, const float* __restrict__ bout,
                             int G) {
    int warp = (blockIdx.x * blockDim.x + threadIdx.x) >> 5;
    int lane = threadIdx.x & 31;
    if (warp >= G) return;
    float cnt = fmaxf(g_cntf[warp], 1.f);
    float inv = 1.f / cnt;
    int c0 = 2 * lane;
    float v0 = g_sums[warp * H + c0] * inv;
    float v1 = g_sums[warp * H + c0 + 1] * inv;
    float sum = v0 + v1;
    #pragma unroll
    for (int d = 16; d > 0; d >>= 1) sum += __shfl_xor_sync(0xffffffffu, sum, d);
    float mu = sum * (1.f / 64.f);
    float d0 = v0 - mu, d1 = v1 - mu;
    float var = d0 * d0 + d1 * d1;
    #pragma unroll
    for (int d = 16; d > 0; d >>= 1) var += __shfl_xor_sync(0xffffffffu, var, d);
    var *= (1.f / 64.f);
    float rstd = rsqrtf(var + 1e-5f);
    float y = d0 * rstd * Wout[c0] + d1 * rstd * Wout[c0 + 1];
    #pragma unroll
    for (int d = 16; d > 0; d >>= 1) y += __shfl_xor_sync(0xffffffffu, y, d);
    if (lane == 0) out[warp] = y + bout[0];
}

// ---------------- driver -----------------------------------------------------
extern "C" void kernel_launch(void* const* d_in, const int* in_sizes, int n_in,
                              void* d_out, int out_size) {
    const float* x         = (const float*)d_in[0];
    const int*   edge_index= (const int*)  d_in[1];
    const float* edge_attr = (const float*)d_in[2];
    const int*   batch     = (const int*)  d_in[3];
    const float* W_in      = (const float*)d_in[4];
    const float* b_in      = (const float*)d_in[5];
    const float* We        = (const float*)d_in[6];
    const float* be        = (const float*)d_in[7];
    const float* W1        = (const float*)d_in[8];
    const float* b1        = (const float*)d_in[9];
    const float* W2        = (const float*)d_in[10];
    const float* b2        = (const float*)d_in[11];
    const float* W_out     = (const float*)d_in[12];
    const float* b_out     = (const float*)d_in[13];
    float* out = (float*)d_out;

    int N = in_sizes[0] / 32;
    int E = in_sizes[1] / 2;
    int G = out_size;
    const int* src = edge_index;
    const int* dst = edge_index + E;

    // --- init + CSR build by dst (edges constant across layers) ---
    init_kernel<<<400, 256>>>(N, G * H);                       // launch 0
    hist_kernel<<<2048, 256>>>(dst, E);                        // launch 1
    scan_kernel<<<1, 1024>>>(N);                               // launch 2
    fill_kernel<<<2048, 256>>>(src, dst, edge_attr, E);        // launch 3
    inproj_kernel<<<1184, 256>>>(x, W_in, b_in, N);            // launch 4

    // --- 5 GINE layers (launch 5 = first agg, for ncu -s 5) ---
    int ntiles = (N + TILE_NODES - 1) / TILE_NODES;
    for (int l = 0; l < 5; ++l) {
        agg_kernel<<<(N + 7) / 8, 256>>>(We + l * 4 * 64, be + l * 64, N);
        mlp_kernel<<<740, 256>>>(W1 + l * 64 * 64, b1 + l * 64,
                                 W2 + l * 64 * 64, b2 + l * 64,
                                 batch, (l == 4) ? 1 : 0, N, ntiles, l);
    }

    // --- counts + layernorm + output ---
    count_kernel<<<(G + 255) / 256, 256>>>(batch, N, G);
    final_kernel<<<(G * 32 + 255) / 256, 256>>>(out, W_out, b_out, G);
}